// round 1
// baseline (speedup 1.0000x reference)
#include <cuda_runtime.h>
#include <math.h>

#define N_NODES 100000
#define N_EDGES 1000000
#define F 32
#define DFEAT 160            // 5 segments x 32
#define BM 128               // GEMM M tile

// ---------------- scratch (device globals; no allocation) ----------------
__device__ __align__(16) float g_deg[2 * N_NODES];        // [deg_out | deg_in]
__device__ __align__(16) float g_norm[2 * N_EDGES];       // [norm_out | norm_in]
__device__ __align__(16) float g_T1o[N_NODES * F];
__device__ __align__(16) float g_T1i[N_NODES * F];
__device__ __align__(16) float g_P2o[N_NODES * F];
__device__ __align__(16) float g_P2i[N_NODES * F];
__device__ __align__(16) float g_W[DFEAT * 64];           // [f][64]: 0-31 Wz_eff, 32-63 Wh_eff

// ---------------- helpers ----------------
__device__ __forceinline__ void red4(float* p, float a, float b, float c, float d) {
    asm volatile("red.global.add.v4.f32 [%0], {%1,%2,%3,%4};"
                 :: "l"(p), "f"(a), "f"(b), "f"(c), "f"(d) : "memory");
}

// ---------------- kernels ----------------
__global__ void zero_kernel() {
    int i = blockIdx.x * blockDim.x + threadIdx.x;   // float4 index
    float4 z = make_float4(0.f, 0.f, 0.f, 0.f);
    if (i < N_NODES * 8) {
        ((float4*)g_T1o)[i] = z;
        ((float4*)g_T1i)[i] = z;
        ((float4*)g_P2o)[i] = z;
        ((float4*)g_P2i)[i] = z;
    }
    if (i < (2 * N_NODES) / 4) ((float4*)g_deg)[i] = z;
}

__global__ void deg_kernel(const int* __restrict__ src, const int* __restrict__ dst,
                           const float* __restrict__ ew) {
    int e = blockIdx.x * blockDim.x + threadIdx.x;
    if (e >= N_EDGES) return;
    float w = ew[e];
    atomicAdd(&g_deg[src[e]], w);
    atomicAdd(&g_deg[N_NODES + dst[e]], w);
}

__global__ void norm_kernel(const int* __restrict__ src, const int* __restrict__ dst,
                            const float* __restrict__ ew) {
    int e = blockIdx.x * blockDim.x + threadIdx.x;
    if (e >= N_EDGES) return;
    float w = ew[e];
    g_norm[e]            = w / g_deg[src[e]];
    g_norm[N_EDGES + e]  = w / g_deg[N_NODES + dst[e]];
}

// hop 1: T1o[dst] += norm_out * X[src]; T1i[src] += norm_in * X[dst]
__global__ void prop1_kernel(const float* __restrict__ X,
                             const int* __restrict__ src, const int* __restrict__ dst) {
    long idx = (long)blockIdx.x * blockDim.x + threadIdx.x;
    int e = (int)(idx >> 3);
    if (e >= N_EDGES) return;
    int q = (int)(idx & 7);
    int s = src[e], d = dst[e];
    float no = g_norm[e], ni = g_norm[N_EDGES + e];
    float4 a = ((const float4*)X)[s * 8 + q];
    red4(&g_T1o[d * F + q * 4], a.x * no, a.y * no, a.z * no, a.w * no);
    float4 b = ((const float4*)X)[d * 8 + q];
    red4(&g_T1i[s * F + q * 4], b.x * ni, b.y * ni, b.z * ni, b.w * ni);
}

// hop 2: P2o[dst] += norm_out * T1o[src]; P2i[src] += norm_in * T1i[dst]
__global__ void prop2_kernel(const int* __restrict__ src, const int* __restrict__ dst) {
    long idx = (long)blockIdx.x * blockDim.x + threadIdx.x;
    int e = (int)(idx >> 3);
    if (e >= N_EDGES) return;
    int q = (int)(idx & 7);
    int s = src[e], d = dst[e];
    float no = g_norm[e], ni = g_norm[N_EDGES + e];
    float4 a = ((const float4*)g_T1o)[s * 8 + q];
    red4(&g_P2o[d * F + q * 4], a.x * no, a.y * no, a.z * no, a.w * no);
    float4 b = ((const float4*)g_T1i)[d * 8 + q];
    red4(&g_P2i[s * F + q * 4], b.x * ni, b.y * ni, b.z * ni, b.w * ni);
}

// Build W_eff[160][64].  W layout: [2][3][64][32], only i<32 rows matter (H-half is zero).
// Row blocks: 0: W00+W10-W02-W12 | 1: W01 | 2: W11 | 3: 2*W02 | 4: 2*W12
__global__ void wprep_kernel(const float* __restrict__ Wz, const float* __restrict__ Wh) {
    int idx = blockIdx.x * blockDim.x + threadIdx.x;
    if (idx >= 2 * DFEAT * F) return;
    int gate = idx / (DFEAT * F);
    int rem  = idx % (DFEAT * F);
    int f = rem / F, j = rem % F;
    int seg = f >> 5, r = f & 31;
    const float* W = gate ? Wh : Wz;
    // (d*3+k) block index, each block is 64*32 = 2048 floats
    float v;
    if (seg == 0)      v = W[(0 * 64 + r) * 32 + j] + W[(3 * 64 + r) * 32 + j]
                         - W[(2 * 64 + r) * 32 + j] - W[(5 * 64 + r) * 32 + j];
    else if (seg == 1) v = W[(1 * 64 + r) * 32 + j];
    else if (seg == 2) v = W[(4 * 64 + r) * 32 + j];
    else if (seg == 3) v = 2.f * W[(2 * 64 + r) * 32 + j];
    else               v = 2.f * W[(5 * 64 + r) * 32 + j];
    g_W[f * 64 + gate * 32 + j] = v;
}

// Fused GEMM [BM x 160] @ [160 x 64] + GRU epilogue + relu + linear head.
// 128 threads: ty=tid>>3 (16, M dim, 8 rows each), tx=tid&7 (8, owns cols {4tx..4tx+3} of
// both the z half and the h half).
__global__ __launch_bounds__(128) void gemm_kernel(
    const float* __restrict__ X,
    const float* __restrict__ bz, const float* __restrict__ bh,
    const float* __restrict__ wl, const float* __restrict__ bl,
    float* __restrict__ out)
{
    __shared__ float As[32][BM + 1];   // [kk][m], +1 pad -> conflict-free
    __shared__ float Bs[32][64];

    int tid = threadIdx.x;
    int tx = tid & 7;
    int ty = tid >> 3;
    int m0 = ty * 8;
    int blockm = blockIdx.x * BM;

    float acc[8][8];
#pragma unroll
    for (int i = 0; i < 8; i++)
#pragma unroll
        for (int j = 0; j < 8; j++) acc[i][j] = 0.f;

    const float* segp[5] = { X, g_T1o, g_T1i, g_P2o, g_P2i };

    for (int ks = 0; ks < 5; ks++) {
        const float* A = segp[ks];
        // A tile: 128 nodes x 32 feats, stored transposed As[kk][m]
#pragma unroll
        for (int i = 0; i < 8; i++) {
            int idx = i * 128 + tid;          // 0..1023
            int m  = idx >> 3;
            int f4 = idx & 7;
            int node = blockm + m;
            float4 v = (node < N_NODES) ? ((const float4*)A)[node * 8 + f4]
                                        : make_float4(0.f, 0.f, 0.f, 0.f);
            As[f4 * 4 + 0][m] = v.x;
            As[f4 * 4 + 1][m] = v.y;
            As[f4 * 4 + 2][m] = v.z;
            As[f4 * 4 + 3][m] = v.w;
        }
        // B tile: 32 x 64 from g_W rows ks*32..ks*32+31 (contiguous)
#pragma unroll
        for (int i = 0; i < 4; i++) {
            int idx = i * 128 + tid;          // float4 index, 0..511
            ((float4*)Bs)[idx] = ((const float4*)g_W)[ks * 512 + idx];
        }
        __syncthreads();

#pragma unroll 4
        for (int kk = 0; kk < 32; kk++) {
            float a[8];
#pragma unroll
            for (int i = 0; i < 8; i++) a[i] = As[kk][m0 + i];
            float4 vz = *(const float4*)&Bs[kk][tx * 4];
            float4 vh = *(const float4*)&Bs[kk][32 + tx * 4];
            float b[8] = { vz.x, vz.y, vz.z, vz.w, vh.x, vh.y, vh.z, vh.w };
#pragma unroll
            for (int i = 0; i < 8; i++)
#pragma unroll
                for (int j = 0; j < 8; j++)
                    acc[i][j] = fmaf(a[i], b[j], acc[i][j]);
        }
        __syncthreads();
    }

    // epilogue: z = sigmoid(gz), ht = tanh(gh), H = (1-z)*ht, y = relu(H) . wl + bl
    float bzv[4], bhv[4], wlv[4];
#pragma unroll
    for (int jj = 0; jj < 4; jj++) {
        int j = tx * 4 + jj;
        bzv[jj] = bz[j];
        bhv[jj] = bh[j];
        wlv[jj] = wl[j];
    }
    float bl0 = bl[0];

#pragma unroll
    for (int i = 0; i < 8; i++) {
        float y = 0.f;
#pragma unroll
        for (int jj = 0; jj < 4; jj++) {
            float gz = acc[i][jj] + bzv[jj];
            float gh = acc[i][jj + 4] + bhv[jj];
            float z  = 1.f / (1.f + expf(-gz));
            float ht = tanhf(gh);
            float Hv = (1.f - z) * ht;
            y += fmaxf(Hv, 0.f) * wlv[jj];
        }
        // reduce over the 8 tx lanes (consecutive within warp)
        y += __shfl_xor_sync(0xffffffffu, y, 4);
        y += __shfl_xor_sync(0xffffffffu, y, 2);
        y += __shfl_xor_sync(0xffffffffu, y, 1);
        if (tx == 0) {
            int node = blockm + m0 + i;
            if (node < N_NODES) out[node] = y + bl0;
        }
    }
}

// ---------------- launch ----------------
extern "C" void kernel_launch(void* const* d_in, const int* in_sizes, int n_in,
                              void* d_out, int out_size) {
    const float* x  = (const float*)d_in[0];
    const int*   ei = (const int*)d_in[1];
    const float* ew = (const float*)d_in[2];
    // d_in[3]=h, d_in[4]=c unused (reference forces H0 = 0)
    const float* Wz = (const float*)d_in[5];
    const float* bz = (const float*)d_in[6];
    // d_in[7]=Wr, d_in[8]=br dead (R * H0 == 0)
    const float* Wh = (const float*)d_in[9];
    const float* bh = (const float*)d_in[10];
    const float* Wl = (const float*)d_in[11];
    const float* bl = (const float*)d_in[12];
    float* out = (float*)d_out;

    const int* src = ei;
    const int* dst = ei + N_EDGES;

    zero_kernel<<<(N_NODES * 8 + 255) / 256, 256>>>();
    deg_kernel<<<(N_EDGES + 255) / 256, 256>>>(src, dst, ew);
    norm_kernel<<<(N_EDGES + 255) / 256, 256>>>(src, dst, ew);
    prop1_kernel<<<(N_EDGES * 8 + 255) / 256, 256>>>(x, src, dst);
    prop2_kernel<<<(N_EDGES * 8 + 255) / 256, 256>>>(src, dst);
    wprep_kernel<<<(2 * DFEAT * F + 255) / 256, 256>>>(Wz, Wh);
    gemm_kernel<<<(N_NODES + BM - 1) / BM, 128>>>(x, bz, bh, Wl, bl, out);
}